// round 1
// baseline (speedup 1.0000x reference)
#include <cuda_runtime.h>
#include <math.h>

// GRU: inputs[64,512,1024], h0[1,64,1024], weight_ih[3072,1024], weight_hh[3072,1024],
//      bias_ih[3072], bias_hh[3072]
// out = concat(outputs[64,512,1024], hn[1,64,1024])

#define BATCH 64
#define SEQ   512
#define IDIM  1024
#define HID   1024
#define G3    3072

// Scratch for x_proj = inputs @ W_ih^T + b_ih : [B*S, 3072] fp32 (402 MB)
__device__ float g_xproj[(size_t)BATCH * SEQ * G3];

// ---------------------------------------------------------------------------
// x_proj SGEMM: C[m][n] = sum_k A[m][k] * W[n][k] + bias[n]
// A = inputs [32768,1024], W = weight_ih [3072,1024]
// BM=BN=128, BK=16, 256 threads, 8x8 microtile.
// ---------------------------------------------------------------------------
__global__ __launch_bounds__(256, 2)
void xproj_kernel(const float* __restrict__ A,
                  const float* __restrict__ W,
                  const float* __restrict__ bias)
{
    __shared__ float As[16][132];
    __shared__ float Bs[16][132];

    const int bm = blockIdx.y;   // 0..255  (M tiles)
    const int bn = blockIdx.x;   // 0..23   (N tiles)
    const int tid = threadIdx.x;
    const int tx = tid & 15;
    const int ty = tid >> 4;

    float acc[8][8];
    #pragma unroll
    for (int i = 0; i < 8; i++)
        #pragma unroll
        for (int j = 0; j < 8; j++) acc[i][j] = 0.f;

    const float* Abase = A + (size_t)bm * 128 * IDIM;
    const float* Wbase = W + (size_t)bn * 128 * IDIM;

    for (int k0 = 0; k0 < IDIM; k0 += 16) {
        // Load 128x16 tiles of A and W, stored K-major (transposed) in smem.
        #pragma unroll
        for (int r = 0; r < 2; r++) {
            int idx = tid + r * 256;      // 0..511 float4 slots
            int row = idx >> 2;           // 0..127
            int kq  = idx & 3;            // 0..3
            float4 va = *(const float4*)(Abase + (size_t)row * IDIM + k0 + kq * 4);
            As[kq * 4 + 0][row] = va.x; As[kq * 4 + 1][row] = va.y;
            As[kq * 4 + 2][row] = va.z; As[kq * 4 + 3][row] = va.w;
            float4 vw = *(const float4*)(Wbase + (size_t)row * IDIM + k0 + kq * 4);
            Bs[kq * 4 + 0][row] = vw.x; Bs[kq * 4 + 1][row] = vw.y;
            Bs[kq * 4 + 2][row] = vw.z; Bs[kq * 4 + 3][row] = vw.w;
        }
        __syncthreads();

        #pragma unroll
        for (int kk = 0; kk < 16; kk++) {
            float a[8], b[8];
            *(float4*)&a[0] = *(const float4*)&As[kk][ty * 8];
            *(float4*)&a[4] = *(const float4*)&As[kk][ty * 8 + 4];
            *(float4*)&b[0] = *(const float4*)&Bs[kk][tx * 8];
            *(float4*)&b[4] = *(const float4*)&Bs[kk][tx * 8 + 4];
            #pragma unroll
            for (int i = 0; i < 8; i++)
                #pragma unroll
                for (int j = 0; j < 8; j++)
                    acc[i][j] += a[i] * b[j];
        }
        __syncthreads();
    }

    const int mbase = bm * 128 + ty * 8;
    const int nbase = bn * 128 + tx * 8;
    float bv[8];
    #pragma unroll
    for (int j = 0; j < 8; j++) bv[j] = bias[nbase + j];
    #pragma unroll
    for (int i = 0; i < 8; i++) {
        float* crow = g_xproj + (size_t)(mbase + i) * G3 + nbase;
        #pragma unroll
        for (int j = 0; j < 8; j++)
            crow[j] = acc[i][j] + bv[j];
    }
}

// ---------------------------------------------------------------------------
// One GRU step. Block = all 64 batches x 8 hidden units x 3 gates.
// Grid = 128 blocks (1024/8). 256 threads: warp w owns unit j=w,
// each thread handles 2 batches (b2, b2+1).
// hprev: base pointer with per-batch stride hstride (h0 at t=0, else out slice).
// ---------------------------------------------------------------------------
__global__ __launch_bounds__(256)
void step_kernel(const float* __restrict__ Whh,   // [3072,1024]
                 const float* __restrict__ bhh,   // [3072]
                 const float* __restrict__ hprev, // batch stride = hstride
                 long hstride,
                 float* __restrict__ out,         // d_out base
                 int t)
{
    __shared__ float hs[64][66];     // [k][b], pad 66 so float2 reads stay aligned
    __shared__ float ws[3][64][9];   // [gate][k][j]

    const int tid = threadIdx.x;
    const int j   = tid >> 5;          // 0..7 (one warp per unit)
    const int b2  = (tid & 31) * 2;    // 0,2,...,62
    const int j0  = blockIdx.x * 8;

    float accr0 = 0.f, accr1 = 0.f;
    float accz0 = 0.f, accz1 = 0.f;
    float accn0 = 0.f, accn1 = 0.f;

    for (int k0 = 0; k0 < HID; k0 += 64) {
        // h tile: 64 b x 64 k (coalesced along k, stored transposed)
        #pragma unroll
        for (int r = 0; r < 4; r++) {
            int idx = tid + r * 256;   // 0..1023 float4 slots
            int bb = idx >> 4;
            int kq = idx & 15;
            float4 v = *(const float4*)(hprev + (size_t)bb * hstride + k0 + kq * 4);
            hs[kq * 4 + 0][bb] = v.x; hs[kq * 4 + 1][bb] = v.y;
            hs[kq * 4 + 2][bb] = v.z; hs[kq * 4 + 3][bb] = v.w;
        }
        // weight tiles: 3 gates x 8 units x 64 k = 384 float4
        for (int idx = tid; idx < 24 * 16; idx += 256) {
            int row = idx >> 4;            // 0..23
            int kq  = idx & 15;
            int g   = row >> 3;
            int jj  = row & 7;
            float4 v = *(const float4*)(Whh + (size_t)(g * HID + j0 + jj) * HID + k0 + kq * 4);
            ws[g][kq * 4 + 0][jj] = v.x; ws[g][kq * 4 + 1][jj] = v.y;
            ws[g][kq * 4 + 2][jj] = v.z; ws[g][kq * 4 + 3][jj] = v.w;
        }
        __syncthreads();

        #pragma unroll 16
        for (int kk = 0; kk < 64; kk++) {
            float2 h2 = *(const float2*)&hs[kk][b2];
            float wr = ws[0][kk][j];
            float wz = ws[1][kk][j];
            float wn = ws[2][kk][j];
            accr0 += h2.x * wr;  accr1 += h2.y * wr;
            accz0 += h2.x * wz;  accz1 += h2.y * wz;
            accn0 += h2.x * wn;  accn1 += h2.y * wn;
        }
        __syncthreads();
    }

    const int jg = j0 + j;
    const float bhr = bhh[jg];
    const float bhz = bhh[HID + jg];
    const float bhn = bhh[2 * HID + jg];
    const float* xg = g_xproj + (size_t)t * G3;   // batch stride SEQ*G3
    float* hout = out + (size_t)t * HID;          // batch stride SEQ*HID

    #pragma unroll
    for (int u = 0; u < 2; u++) {
        int bb = b2 + u;
        float ar = u ? accr1 : accr0;
        float az = u ? accz1 : accz0;
        float an = u ? accn1 : accn0;
        const float* xrow = xg + (size_t)bb * SEQ * G3;
        float xr = xrow[jg];
        float xz = xrow[HID + jg];
        float xn = xrow[2 * HID + jg];
        float r = 1.f / (1.f + expf(-(xr + ar + bhr)));
        float z = 1.f / (1.f + expf(-(xz + az + bhz)));
        float n = tanhf(xn + r * (an + bhn));
        float hp = hprev[(size_t)bb * hstride + jg];
        float hnew = (1.f - z) * n + z * hp;
        hout[(size_t)bb * SEQ * HID + jg] = hnew;
    }
}

// Gather h_{SEQ-1} (strided in out) into the contiguous hn region.
__global__ void hn_kernel(float* __restrict__ out)
{
    int i = blockIdx.x * 256 + threadIdx.x;   // 0..65535
    int b = i >> 10;
    int jj = i & 1023;
    out[(size_t)BATCH * SEQ * HID + i] =
        out[((size_t)b * SEQ + (SEQ - 1)) * HID + jj];
}

// ---------------------------------------------------------------------------
extern "C" void kernel_launch(void* const* d_in, const int* in_sizes, int n_in,
                              void* d_out, int out_size)
{
    const float* inputs = (const float*)d_in[0];   // [64,512,1024]
    const float* h0     = (const float*)d_in[1];   // [1,64,1024]
    const float* wih    = (const float*)d_in[2];   // [3072,1024]
    const float* whh    = (const float*)d_in[3];   // [3072,1024]
    const float* bih    = (const float*)d_in[4];   // [3072]
    const float* bhh    = (const float*)d_in[5];   // [3072]
    float* out = (float*)d_out;

    // Phase 1: x_proj = inputs @ W_ih^T + b_ih
    dim3 grid_x(G3 / 128, (BATCH * SEQ) / 128);    // (24, 256)
    xproj_kernel<<<grid_x, 256>>>(inputs, wih, bih);

    // Phase 2: sequential recurrence; h_t is carried inside `out`.
    for (int t = 0; t < SEQ; t++) {
        const float* hprev = (t == 0) ? h0 : (out + (size_t)(t - 1) * HID);
        long hstride = (t == 0) ? (long)HID : (long)SEQ * HID;
        step_kernel<<<HID / 8, 256>>>(whh, bhh, hprev, hstride, out, t);
    }

    // Phase 3: hn = h_{SEQ-1}
    hn_kernel<<<(BATCH * HID) / 256, 256>>>(out);
}

// round 2
// speedup vs baseline: 1.9468x; 1.9468x over previous
#include <cuda_runtime.h>
#include <math.h>
#include <stdint.h>

// GRU: inputs[64,512,1024], h0[1,64,1024], weight_ih[3072,1024], weight_hh[3072,1024],
//      bias_ih[3072], bias_hh[3072]
// out = concat(outputs[64,512,1024], hn[1,64,1024])

#define BATCH 64
#define SEQ   512
#define IDIM  1024
#define HID   1024
#define G3    3072

// Scratch (device globals; no runtime allocation).
__device__ float g_xproj[(size_t)BATCH * SEQ * G3];   // exact fp32 x_proj
__device__ float g_in_r[(size_t)BATCH * SEQ * IDIM];  // tf32-rounded inputs
__device__ float g_wih_r[(size_t)G3 * IDIM];          // tf32-rounded W_ih
__device__ float g_whh_r[(size_t)G3 * IDIM];          // tf32-rounded W_hh
__device__ float g_hbuf[2][(size_t)BATCH * HID];      // tf32-rounded h ping-pong

// ---------------------------------------------------------------------------
// helpers
// ---------------------------------------------------------------------------
__device__ __forceinline__ float tf32r(float x) {
    uint32_t o;
    asm("cvt.rna.tf32.f32 %0, %1;" : "=r"(o) : "f"(x));
    return __uint_as_float(o);
}

__device__ __forceinline__ uint32_t smem_u32(const void* p) {
    uint32_t a;
    asm("{ .reg .u64 t; cvta.to.shared.u64 t, %1; cvt.u32.u64 %0, t; }"
        : "=r"(a) : "l"(p));
    return a;
}

__device__ __forceinline__ void cpa16(uint32_t dst, const void* src) {
    asm volatile("cp.async.ca.shared.global [%0], [%1], 16;" :: "r"(dst), "l"(src));
}
__device__ __forceinline__ void cpa_commit() {
    asm volatile("cp.async.commit_group;");
}
__device__ __forceinline__ void cpa_wait0() {
    asm volatile("cp.async.wait_group 0;");
}
__device__ __forceinline__ void cpa_wait1() {
    asm volatile("cp.async.wait_group 1;");
}

// D += A(16x8,tf32,row) * B(8x8,tf32,col)
__device__ __forceinline__ void mma8(float* c, const uint32_t* a, uint32_t b0, uint32_t b1) {
    asm volatile(
        "mma.sync.aligned.m16n8k8.row.col.f32.tf32.tf32.f32 "
        "{%0,%1,%2,%3}, {%4,%5,%6,%7}, {%8,%9}, {%0,%1,%2,%3};"
        : "+f"(c[0]), "+f"(c[1]), "+f"(c[2]), "+f"(c[3])
        : "r"(a[0]), "r"(a[1]), "r"(a[2]), "r"(a[3]), "r"(b0), "r"(b1));
}

__device__ __forceinline__ float sigmoidf_(float x) {
    return 1.f / (1.f + __expf(-x));
}

// ---------------------------------------------------------------------------
// tf32 RNA rounding pre-pass (vectorized)
// ---------------------------------------------------------------------------
__global__ void round_kernel(const float4* __restrict__ src, float4* __restrict__ dst, int n4)
{
    int i = blockIdx.x * 256 + threadIdx.x;
    if (i < n4) {
        float4 v = src[i];
        v.x = tf32r(v.x); v.y = tf32r(v.y); v.z = tf32r(v.z); v.w = tf32r(v.w);
        dst[i] = v;
    }
}

// ---------------------------------------------------------------------------
// x_proj GEMM (tf32 mma): C[32768,3072] = A[32768,1024] @ W[3072,1024]^T + bias
// BM=128, BN=64, BK=32, 256 threads (8 warps: 4m x 2n), warp tile 32x32.
// ---------------------------------------------------------------------------
#define XP_BKP 36
__global__ __launch_bounds__(256, 2)
void xproj_tf32(const float* __restrict__ A,
                const float* __restrict__ W,
                const float* __restrict__ bias)
{
    extern __shared__ float sm[];
    float* As = sm;                       // [2][128][36]
    float* Bs = sm + 2 * 128 * XP_BKP;    // [2][64][36]
    const uint32_t asb = smem_u32(As);
    const uint32_t bsb = smem_u32(Bs);

    const int bm = blockIdx.y, bn = blockIdx.x;
    const int tid = threadIdx.x;
    const int w = tid >> 5, lane = tid & 31;
    const int g = lane >> 2, q = lane & 3;
    const int wm = w & 3, wn = w >> 1 & 2 ? 0 : (w >> 2);  // placeholder fix below
    const int wnn = w >> 2;   // 0..1

    const float* Abase = A + (size_t)bm * 128 * IDIM;
    const float* Wbase = W + (size_t)bn * 64 * IDIM;

    float acc[2][4][4];
    #pragma unroll
    for (int i = 0; i < 2; i++)
        #pragma unroll
        for (int j = 0; j < 4; j++)
            #pragma unroll
            for (int k = 0; k < 4; k++) acc[i][j][k] = 0.f;

    // stage loader
    auto load_stage = [&](int kc, int buf) {
        int k0 = kc * 32;
        #pragma unroll
        for (int i = 0; i < 4; i++) {
            int idx = tid + i * 256;         // 0..1023
            int row = idx >> 3, cq = idx & 7;
            cpa16(asb + (((buf * 128 + row) * XP_BKP + cq * 4) << 2),
                  Abase + (size_t)row * IDIM + k0 + cq * 4);
        }
        #pragma unroll
        for (int i = 0; i < 2; i++) {
            int idx = tid + i * 256;         // 0..511
            int row = idx >> 3, cq = idx & 7;
            cpa16(bsb + (((buf * 64 + row) * XP_BKP + cq * 4) << 2),
                  Wbase + (size_t)row * IDIM + k0 + cq * 4);
        }
    };

    load_stage(0, 0);
    cpa_commit();

    for (int kc = 0; kc < 32; kc++) {
        int cur = kc & 1;
        if (kc + 1 < 32) { load_stage(kc + 1, cur ^ 1); cpa_commit(); cpa_wait1(); }
        else             { cpa_wait0(); }
        __syncthreads();

        #pragma unroll
        for (int ks = 0; ks < 4; ks++) {
            uint32_t a[2][4];
            #pragma unroll
            for (int mt = 0; mt < 2; mt++) {
                int r0 = cur * 128 + wm * 32 + mt * 16;
                a[mt][0] = __float_as_uint(As[(r0 + g) * XP_BKP + ks * 8 + q]);
                a[mt][1] = __float_as_uint(As[(r0 + g + 8) * XP_BKP + ks * 8 + q]);
                a[mt][2] = __float_as_uint(As[(r0 + g) * XP_BKP + ks * 8 + q + 4]);
                a[mt][3] = __float_as_uint(As[(r0 + g + 8) * XP_BKP + ks * 8 + q + 4]);
            }
            #pragma unroll
            for (int nt = 0; nt < 4; nt++) {
                int c0 = cur * 64 + wnn * 32 + nt * 8 + g;
                uint32_t b0 = __float_as_uint(Bs[c0 * XP_BKP + ks * 8 + q]);
                uint32_t b1 = __float_as_uint(Bs[c0 * XP_BKP + ks * 8 + q + 4]);
                mma8(acc[0][nt], a[0], b0, b1);
                mma8(acc[1][nt], a[1], b0, b1);
            }
        }
        __syncthreads();
    }

    (void)wm; (void)wn;
    // epilogue
    #pragma unroll
    for (int mt = 0; mt < 2; mt++) {
        #pragma unroll
        for (int nt = 0; nt < 4; nt++) {
            int row = bm * 128 + wm * 32 + mt * 16 + g;
            int col = bn * 64 + wnn * 32 + nt * 8 + 2 * q;
            float b0 = bias[col], b1 = bias[col + 1];
            float2 v0 = make_float2(acc[mt][nt][0] + b0, acc[mt][nt][1] + b1);
            float2 v1 = make_float2(acc[mt][nt][2] + b0, acc[mt][nt][3] + b1);
            *(float2*)(g_xproj + (size_t)row * G3 + col) = v0;
            *(float2*)(g_xproj + (size_t)(row + 8) * G3 + col) = v1;
        }
    }
}

// ---------------------------------------------------------------------------
// One GRU step (tf32 mma). Grid 64 blocks x 16 units; 128 threads (4 warps, m16 each).
// Block computes [64 batch x 48 cols] = 16 units x {r,z,n}, K=1024, BK=64 double-buffered.
// ---------------------------------------------------------------------------
#define ST_BKP 68
__global__ __launch_bounds__(128)
void step_tf32(const float* __restrict__ Whh,   // rounded [3072,1024]
               const float* __restrict__ bhh,
               const float* __restrict__ hrd,   // rounded h_{t-1} [64,1024]
               float* __restrict__ hwr,         // rounded h_t out [64,1024]
               const float* __restrict__ hpx,   // exact h_{t-1}, batch stride hstride
               long hstride,
               float* __restrict__ out,
               int t)
{
    extern __shared__ float sm[];
    float* Hs = sm;                      // [2][64][68]
    float* Ws = sm + 2 * 64 * ST_BKP;    // [2][48][68]
    const uint32_t hsb = smem_u32(Hs);
    const uint32_t wsb = smem_u32(Ws);

    const int tid = threadIdx.x;
    const int w = tid >> 5, lane = tid & 31;
    const int g = lane >> 2, q = lane & 3;
    const int j0 = blockIdx.x * 16;

    float acc[6][4];
    #pragma unroll
    for (int i = 0; i < 6; i++)
        #pragma unroll
        for (int k = 0; k < 4; k++) acc[i][k] = 0.f;

    auto load_stage = [&](int kc, int buf) {
        int k0 = kc * 64;
        #pragma unroll
        for (int i = 0; i < 8; i++) {
            int idx = tid + i * 128;       // 0..1023
            int b = idx >> 4, cq = idx & 15;
            cpa16(hsb + (((buf * 64 + b) * ST_BKP + cq * 4) << 2),
                  hrd + (size_t)b * HID + k0 + cq * 4);
        }
        #pragma unroll
        for (int i = 0; i < 6; i++) {
            int idx = tid + i * 128;       // 0..767
            int r = idx >> 4, cq = idx & 15;
            int gate = r >> 4, u = r & 15;
            cpa16(wsb + (((buf * 48 + r) * ST_BKP + cq * 4) << 2),
                  Whh + (size_t)(gate * HID + j0 + u) * HID + k0 + cq * 4);
        }
    };

    load_stage(0, 0);
    cpa_commit();

    for (int kc = 0; kc < 16; kc++) {
        int cur = kc & 1;
        if (kc + 1 < 16) { load_stage(kc + 1, cur ^ 1); cpa_commit(); cpa_wait1(); }
        else             { cpa_wait0(); }
        __syncthreads();

        #pragma unroll
        for (int ks = 0; ks < 8; ks++) {
            uint32_t a[4];
            int r0 = cur * 64 + w * 16;
            a[0] = __float_as_uint(Hs[(r0 + g) * ST_BKP + ks * 8 + q]);
            a[1] = __float_as_uint(Hs[(r0 + g + 8) * ST_BKP + ks * 8 + q]);
            a[2] = __float_as_uint(Hs[(r0 + g) * ST_BKP + ks * 8 + q + 4]);
            a[3] = __float_as_uint(Hs[(r0 + g + 8) * ST_BKP + ks * 8 + q + 4]);
            #pragma unroll
            for (int nt = 0; nt < 6; nt++) {
                int c0 = cur * 48 + nt * 8 + g;
                uint32_t b0 = __float_as_uint(Ws[c0 * ST_BKP + ks * 8 + q]);
                uint32_t b1 = __float_as_uint(Ws[c0 * ST_BKP + ks * 8 + q + 4]);
                mma8(acc[nt], a, b0, b1);
            }
        }
        __syncthreads();
    }

    // epilogue: lane holds r/z/n for 2 rows x 4 units
    #pragma unroll
    for (int rh = 0; rh < 2; rh++) {
        int b = w * 16 + g + rh * 8;
        const float* xrow = g_xproj + ((size_t)b * SEQ + t) * G3;
        const float* hpq = hpx + (size_t)b * hstride;
        float* orow = out + ((size_t)b * SEQ + t) * HID;
        float* hw = hwr + (size_t)b * HID;
        #pragma unroll
        for (int p = 0; p < 2; p++) {
            #pragma unroll
            for (int e = 0; e < 2; e++) {
                int u = p * 8 + 2 * q + e;
                int j = j0 + u;
                float rp = acc[p][rh * 2 + e];
                float zp = acc[2 + p][rh * 2 + e];
                float np = acc[4 + p][rh * 2 + e];
                float rr = sigmoidf_(xrow[j] + rp + bhh[j]);
                float zz = sigmoidf_(xrow[HID + j] + zp + bhh[HID + j]);
                float nn = tanhf(xrow[2 * HID + j] + rr * (np + bhh[2 * HID + j]));
                float hp = hpq[j];
                float hn = (1.f - zz) * nn + zz * hp;
                orow[j] = hn;
                hw[j] = tf32r(hn);
            }
        }
    }
}

// Gather h_{SEQ-1} into the contiguous hn region.
__global__ void hn_kernel(float* __restrict__ out)
{
    int i = blockIdx.x * 256 + threadIdx.x;   // 0..65535
    int b = i >> 10;
    int jj = i & 1023;
    out[(size_t)BATCH * SEQ * HID + i] =
        out[((size_t)b * SEQ + (SEQ - 1)) * HID + jj];
}

// ---------------------------------------------------------------------------
extern "C" void kernel_launch(void* const* d_in, const int* in_sizes, int n_in,
                              void* d_out, int out_size)
{
    const float* inputs = (const float*)d_in[0];
    const float* h0     = (const float*)d_in[1];
    const float* wih    = (const float*)d_in[2];
    const float* whh    = (const float*)d_in[3];
    const float* bih    = (const float*)d_in[4];
    const float* bhh    = (const float*)d_in[5];
    float* out = (float*)d_out;

    static bool attr_done = false;
    const int XP_SMEM = (2 * 128 * XP_BKP + 2 * 64 * XP_BKP) * 4;   // 55296
    const int ST_SMEM = (2 * 64 * ST_BKP + 2 * 48 * ST_BKP) * 4;    // 60928
    if (!attr_done) {
        cudaFuncSetAttribute(xproj_tf32, cudaFuncAttributeMaxDynamicSharedMemorySize, XP_SMEM);
        cudaFuncSetAttribute(step_tf32, cudaFuncAttributeMaxDynamicSharedMemorySize, ST_SMEM);
        attr_done = true;
    }

    float* in_r;  cudaGetSymbolAddress((void**)&in_r,  g_in_r);
    float* wih_r; cudaGetSymbolAddress((void**)&wih_r, g_wih_r);
    float* whh_r; cudaGetSymbolAddress((void**)&whh_r, g_whh_r);
    float* hbuf;  cudaGetSymbolAddress((void**)&hbuf,  g_hbuf);

    // Phase 0: RNA-round all mma operands once.
    {
        int n4;
        n4 = BATCH * SEQ * IDIM / 4;
        round_kernel<<<(n4 + 255) / 256, 256>>>((const float4*)inputs, (float4*)in_r, n4);
        n4 = G3 * IDIM / 4;
        round_kernel<<<(n4 + 255) / 256, 256>>>((const float4*)wih, (float4*)wih_r, n4);
        round_kernel<<<(n4 + 255) / 256, 256>>>((const float4*)whh, (float4*)whh_r, n4);
        n4 = BATCH * HID / 4;
        round_kernel<<<(n4 + 255) / 256, 256>>>((const float4*)h0, (float4*)hbuf, n4);
    }

    // Phase 1: x_proj
    dim3 grid_x(G3 / 64, (BATCH * SEQ) / 128);    // (48, 256)
    xproj_tf32<<<grid_x, 256, XP_SMEM>>>(in_r, wih_r, bih);

    // Phase 2: recurrence
    for (int t = 0; t < SEQ; t++) {
        const float* hrd = hbuf + (size_t)(t & 1) * BATCH * HID;
        float* hwr = hbuf + (size_t)((t + 1) & 1) * BATCH * HID;
        const float* hpx = (t == 0) ? h0 : (out + (size_t)(t - 1) * HID);
        long hstride = (t == 0) ? (long)HID : (long)SEQ * HID;
        step_tf32<<<64, 128, ST_SMEM>>>(whh_r, bhh, hrd, hwr, hpx, hstride, out, t);
    }

    // Phase 3: hn
    hn_kernel<<<(BATCH * HID) / 256, 256>>>(out);
}

// round 3
// speedup vs baseline: 4.6259x; 2.3761x over previous
#include <cuda_runtime.h>
#include <math.h>
#include <stdint.h>

// GRU: inputs[64,512,1024], h0[1,64,1024], weight_ih[3072,1024], weight_hh[3072,1024],
//      bias_ih[3072], bias_hh[3072]
// out = concat(outputs[64,512,1024], hn[1,64,1024])

#define BATCH 64
#define SEQ   512
#define IDIM  1024
#define HID   1024
#define G3    3072

#define NBLK  128        // persistent blocks (<=148 SMs, 1/SM)
#define UPB   8          // hidden units per block
#define WPAD  1028       // weight smem row stride (conflict-free)
#define HPAD  68         // h smem row stride

// Scratch (device globals; no runtime allocation).
__device__ float g_xproj[(size_t)BATCH * SEQ * G3];   // exact fp32 x_proj
__device__ float g_in_r[(size_t)BATCH * SEQ * IDIM];  // tf32-rounded inputs
__device__ float g_wih_r[(size_t)G3 * IDIM];          // tf32-rounded W_ih
__device__ float g_whh_r[(size_t)G3 * IDIM];          // tf32-rounded W_hh
__device__ float g_h[2][(size_t)BATCH * HID];         // tf32-rounded h ping-pong
__device__ int      g_bar_count;
__device__ unsigned g_bar_gen;

// ---------------------------------------------------------------------------
// helpers
// ---------------------------------------------------------------------------
__device__ __forceinline__ float tf32r(float x) {
    uint32_t o;
    asm("cvt.rna.tf32.f32 %0, %1;" : "=r"(o) : "f"(x));
    return __uint_as_float(o);
}
__device__ __forceinline__ uint32_t smem_u32(const void* p) {
    uint32_t a;
    asm("{ .reg .u64 t; cvta.to.shared.u64 t, %1; cvt.u32.u64 %0, t; }" : "=r"(a) : "l"(p));
    return a;
}
__device__ __forceinline__ void cpa16(uint32_t dst, const void* src) {
    asm volatile("cp.async.ca.shared.global [%0], [%1], 16;" :: "r"(dst), "l"(src));
}
__device__ __forceinline__ void cpa_commit() { asm volatile("cp.async.commit_group;"); }
__device__ __forceinline__ void cpa_wait0()  { asm volatile("cp.async.wait_group 0;"); }
__device__ __forceinline__ void cpa_wait1()  { asm volatile("cp.async.wait_group 1;"); }

__device__ __forceinline__ void mma8(float* c, const uint32_t* a, uint32_t b0, uint32_t b1) {
    asm volatile(
        "mma.sync.aligned.m16n8k8.row.col.f32.tf32.tf32.f32 "
        "{%0,%1,%2,%3}, {%4,%5,%6,%7}, {%8,%9}, {%0,%1,%2,%3};"
        : "+f"(c[0]), "+f"(c[1]), "+f"(c[2]), "+f"(c[3])
        : "r"(a[0]), "r"(a[1]), "r"(a[2]), "r"(a[3]), "r"(b0), "r"(b1));
}
__device__ __forceinline__ float sigmoidf_(float x) { return 1.f / (1.f + __expf(-x)); }

__device__ __forceinline__ void grid_barrier() {
    __syncthreads();
    if (threadIdx.x == 0) {
        __threadfence();
        unsigned gen;
        asm volatile("ld.acquire.gpu.u32 %0, [%1];" : "=r"(gen) : "l"(&g_bar_gen));
        int prev = atomicAdd(&g_bar_count, 1);
        if (prev == NBLK - 1) {
            atomicExch(&g_bar_count, 0);
            asm volatile("st.release.gpu.u32 [%0], %1;" :: "l"(&g_bar_gen), "r"(gen + 1));
        } else {
            unsigned cur;
            do {
                __nanosleep(64);
                asm volatile("ld.acquire.gpu.u32 %0, [%1];" : "=r"(cur) : "l"(&g_bar_gen));
            } while (cur == gen);
        }
    }
    __syncthreads();
}

// ---------------------------------------------------------------------------
// tf32 RNA rounding pre-pass
// ---------------------------------------------------------------------------
__global__ void round_kernel(const float4* __restrict__ src, float4* __restrict__ dst, int n4)
{
    int i = blockIdx.x * 256 + threadIdx.x;
    if (i < n4) {
        float4 v = src[i];
        v.x = tf32r(v.x); v.y = tf32r(v.y); v.z = tf32r(v.z); v.w = tf32r(v.w);
        dst[i] = v;
    }
}

// ---------------------------------------------------------------------------
// x_proj GEMM (tf32 mma): C[32768,3072] = A @ W^T + bias. BM=128 BN=64 BK=32.
// ---------------------------------------------------------------------------
#define XP_BKP 36
__global__ __launch_bounds__(256, 2)
void xproj_tf32(const float* __restrict__ A,
                const float* __restrict__ W,
                const float* __restrict__ bias)
{
    extern __shared__ float sm[];
    float* As = sm;                       // [2][128][36]
    float* Bs = sm + 2 * 128 * XP_BKP;    // [2][64][36]
    const uint32_t asb = smem_u32(As);
    const uint32_t bsb = smem_u32(Bs);

    const int bm = blockIdx.y, bn = blockIdx.x;
    const int tid = threadIdx.x;
    const int w = tid >> 5, lane = tid & 31;
    const int g = lane >> 2, q = lane & 3;
    const int wm = w & 3;
    const int wnn = w >> 2;

    const float* Abase = A + (size_t)bm * 128 * IDIM;
    const float* Wbase = W + (size_t)bn * 64 * IDIM;

    float acc[2][4][4];
    #pragma unroll
    for (int i = 0; i < 2; i++)
        #pragma unroll
        for (int j = 0; j < 4; j++)
            #pragma unroll
            for (int k = 0; k < 4; k++) acc[i][j][k] = 0.f;

    auto load_stage = [&](int kc, int buf) {
        int k0 = kc * 32;
        #pragma unroll
        for (int i = 0; i < 4; i++) {
            int idx = tid + i * 256;
            int row = idx >> 3, cq = idx & 7;
            cpa16(asb + (((buf * 128 + row) * XP_BKP + cq * 4) << 2),
                  Abase + (size_t)row * IDIM + k0 + cq * 4);
        }
        #pragma unroll
        for (int i = 0; i < 2; i++) {
            int idx = tid + i * 256;
            int row = idx >> 3, cq = idx & 7;
            cpa16(bsb + (((buf * 64 + row) * XP_BKP + cq * 4) << 2),
                  Wbase + (size_t)row * IDIM + k0 + cq * 4);
        }
    };

    load_stage(0, 0);
    cpa_commit();

    for (int kc = 0; kc < 32; kc++) {
        int cur = kc & 1;
        if (kc + 1 < 32) { load_stage(kc + 1, cur ^ 1); cpa_commit(); cpa_wait1(); }
        else             { cpa_wait0(); }
        __syncthreads();

        #pragma unroll
        for (int ks = 0; ks < 4; ks++) {
            uint32_t a[2][4];
            #pragma unroll
            for (int mt = 0; mt < 2; mt++) {
                int r0 = cur * 128 + wm * 32 + mt * 16;
                a[mt][0] = __float_as_uint(As[(r0 + g) * XP_BKP + ks * 8 + q]);
                a[mt][1] = __float_as_uint(As[(r0 + g + 8) * XP_BKP + ks * 8 + q]);
                a[mt][2] = __float_as_uint(As[(r0 + g) * XP_BKP + ks * 8 + q + 4]);
                a[mt][3] = __float_as_uint(As[(r0 + g + 8) * XP_BKP + ks * 8 + q + 4]);
            }
            #pragma unroll
            for (int nt = 0; nt < 4; nt++) {
                int c0 = cur * 64 + wnn * 32 + nt * 8 + g;
                uint32_t b0 = __float_as_uint(Bs[c0 * XP_BKP + ks * 8 + q]);
                uint32_t b1 = __float_as_uint(Bs[c0 * XP_BKP + ks * 8 + q + 4]);
                mma8(acc[0][nt], a[0], b0, b1);
                mma8(acc[1][nt], a[1], b0, b1);
            }
        }
        __syncthreads();
    }

    #pragma unroll
    for (int mt = 0; mt < 2; mt++) {
        #pragma unroll
        for (int nt = 0; nt < 4; nt++) {
            int row = bm * 128 + wm * 32 + mt * 16 + g;
            int col = bn * 64 + wnn * 32 + nt * 8 + 2 * q;
            float b0 = bias[col], b1 = bias[col + 1];
            float2 v0 = make_float2(acc[mt][nt][0] + b0, acc[mt][nt][1] + b1);
            float2 v1 = make_float2(acc[mt][nt][2] + b0, acc[mt][nt][3] + b1);
            *(float2*)(g_xproj + (size_t)row * G3 + col) = v0;
            *(float2*)(g_xproj + (size_t)(row + 8) * G3 + col) = v1;
        }
    }
}

// ---------------------------------------------------------------------------
// Persistent GRU recurrence: 128 blocks x 128 threads, all 512 steps.
// Block bid owns units j0=bid*8 (x3 gates = 24 GEMM cols) for all 64 batches.
// W_hh slice resident in smem for the whole kernel. h streamed per step.
// ---------------------------------------------------------------------------
__global__ __launch_bounds__(128, 1)
void gru_persistent(const float* __restrict__ Whh_r,  // tf32-rounded [3072,1024]
                    const float* __restrict__ bhh,
                    const float* __restrict__ h0,     // exact [64,1024]
                    float* __restrict__ out)
{
    extern __shared__ float sm[];
    float* Ws = sm;                    // [24][WPAD]
    float* Hs = sm + 24 * WPAD;        // [2][64][HPAD]
    const uint32_t wsb = smem_u32(Ws);
    const uint32_t hsb = smem_u32(Hs);

    const int tid = threadIdx.x;
    const int w = tid >> 5, lane = tid & 31;
    const int g = lane >> 2, q = lane & 3;
    const int j0 = blockIdx.x * UPB;
    const int jc = j0 + 2 * q;                 // float2 column base this thread owns
    const int brow[2] = { w * 16 + g, w * 16 + g + 8 };

    // ---- load resident weights: 24 rows x 1024 (6144 float4) ----
    for (int i = tid; i < 24 * 256; i += 128) {
        int r = i >> 8, cq = i & 255;
        int gate = r >> 3, u = r & 7;
        cpa16(wsb + ((r * WPAD + cq * 4) << 2),
              Whh_r + (size_t)(gate * HID + j0 + u) * HID + cq * 4);
    }
    cpa_commit();
    cpa_wait0();
    __syncthreads();

    // ---- per-thread persistent state: exact h and biases ----
    float2 hp2[2];
    #pragma unroll
    for (int rh = 0; rh < 2; rh++)
        hp2[rh] = *(const float2*)(h0 + (size_t)brow[rh] * HID + jc);
    float2 bh2[3];
    #pragma unroll
    for (int gate = 0; gate < 3; gate++)
        bh2[gate] = *(const float2*)(bhh + gate * HID + jc);

    float* ghb = &g_h[0][0];

    for (int t = 0; t < SEQ; t++) {
        const float* hread = ghb + (size_t)(t & 1) * BATCH * HID;
        float* hwrite      = ghb + (size_t)((t + 1) & 1) * BATCH * HID;

        // prefetch x_proj gate values for this step (used in epilogue)
        float2 xg[2][3];
        #pragma unroll
        for (int rh = 0; rh < 2; rh++)
            #pragma unroll
            for (int gate = 0; gate < 3; gate++)
                xg[rh][gate] = *(const float2*)(g_xproj +
                    ((size_t)brow[rh] * SEQ + t) * G3 + gate * HID + jc);

        // stage 0 of h
        {
            #pragma unroll
            for (int i = 0; i < 8; i++) {
                int idx = tid + i * 128;
                int b = idx >> 4, cq = idx & 15;
                cpa16(hsb + (((0 * 64 + b) * HPAD + cq * 4) << 2),
                      hread + (size_t)b * HID + cq * 4);
            }
            cpa_commit();
        }

        float acc[3][4];
        #pragma unroll
        for (int i = 0; i < 3; i++)
            #pragma unroll
            for (int k = 0; k < 4; k++) acc[i][k] = 0.f;

        for (int kc = 0; kc < 16; kc++) {
            int cur = kc & 1;
            if (kc + 1 < 16) {
                int k0 = (kc + 1) * 64, buf = cur ^ 1;
                #pragma unroll
                for (int i = 0; i < 8; i++) {
                    int idx = tid + i * 128;
                    int b = idx >> 4, cq = idx & 15;
                    cpa16(hsb + (((buf * 64 + b) * HPAD + cq * 4) << 2),
                          hread + (size_t)b * HID + k0 + cq * 4);
                }
                cpa_commit();
                cpa_wait1();
            } else {
                cpa_wait0();
            }
            __syncthreads();

            #pragma unroll
            for (int ks = 0; ks < 8; ks++) {
                uint32_t a[4];
                int r0 = cur * 64 + w * 16;
                a[0] = __float_as_uint(Hs[(r0 + g) * HPAD + ks * 8 + q]);
                a[1] = __float_as_uint(Hs[(r0 + g + 8) * HPAD + ks * 8 + q]);
                a[2] = __float_as_uint(Hs[(r0 + g) * HPAD + ks * 8 + q + 4]);
                a[3] = __float_as_uint(Hs[(r0 + g + 8) * HPAD + ks * 8 + q + 4]);
                int koff = kc * 64 + ks * 8 + q;
                #pragma unroll
                for (int nt = 0; nt < 3; nt++) {
                    uint32_t b0 = __float_as_uint(Ws[(nt * 8 + g) * WPAD + koff]);
                    uint32_t b1 = __float_as_uint(Ws[(nt * 8 + g) * WPAD + koff + 4]);
                    mma8(acc[nt], a, b0, b1);
                }
            }
            __syncthreads();
        }

        // ---- epilogue: gates + state update ----
        #pragma unroll
        for (int rh = 0; rh < 2; rh++) {
            float hx[2], hr[2];
            #pragma unroll
            for (int e = 0; e < 2; e++) {
                float xr = e ? xg[rh][0].y : xg[rh][0].x;
                float xz = e ? xg[rh][1].y : xg[rh][1].x;
                float xn = e ? xg[rh][2].y : xg[rh][2].x;
                float br = e ? bh2[0].y : bh2[0].x;
                float bz = e ? bh2[1].y : bh2[1].x;
                float bn = e ? bh2[2].y : bh2[2].x;
                float hp = e ? hp2[rh].y : hp2[rh].x;
                float rr = sigmoidf_(xr + acc[0][rh * 2 + e] + br);
                float zz = sigmoidf_(xz + acc[1][rh * 2 + e] + bz);
                float nn = tanhf(xn + rr * (acc[2][rh * 2 + e] + bn));
                float hv = (1.f - zz) * nn + zz * hp;
                hx[e] = hv;
                hr[e] = tf32r(hv);
            }
            hp2[rh] = make_float2(hx[0], hx[1]);
            *(float2*)(out + ((size_t)brow[rh] * SEQ + t) * HID + jc) =
                make_float2(hx[0], hx[1]);
            *(float2*)(hwrite + (size_t)brow[rh] * HID + jc) =
                make_float2(hr[0], hr[1]);
        }

        grid_barrier();
    }
}

// Gather h_{SEQ-1} into the contiguous hn region.
__global__ void hn_kernel(float* __restrict__ out)
{
    int i = blockIdx.x * 256 + threadIdx.x;
    int b = i >> 10;
    int jj = i & 1023;
    out[(size_t)BATCH * SEQ * HID + i] =
        out[((size_t)b * SEQ + (SEQ - 1)) * HID + jj];
}

// ---------------------------------------------------------------------------
extern "C" void kernel_launch(void* const* d_in, const int* in_sizes, int n_in,
                              void* d_out, int out_size)
{
    const float* inputs = (const float*)d_in[0];
    const float* h0     = (const float*)d_in[1];
    const float* wih    = (const float*)d_in[2];
    const float* whh    = (const float*)d_in[3];
    const float* bih    = (const float*)d_in[4];
    const float* bhh    = (const float*)d_in[5];
    float* out = (float*)d_out;

    const int XP_SMEM = (2 * 128 * XP_BKP + 2 * 64 * XP_BKP) * 4;           // 55296
    const int GP_SMEM = (24 * WPAD + 2 * 64 * HPAD) * 4;                    // 133504
    static bool attr_done = false;
    if (!attr_done) {
        cudaFuncSetAttribute(xproj_tf32, cudaFuncAttributeMaxDynamicSharedMemorySize, XP_SMEM);
        cudaFuncSetAttribute(gru_persistent, cudaFuncAttributeMaxDynamicSharedMemorySize, GP_SMEM);
        attr_done = true;
    }

    float* in_r;  cudaGetSymbolAddress((void**)&in_r,  g_in_r);
    float* wih_r; cudaGetSymbolAddress((void**)&wih_r, g_wih_r);
    float* whh_r; cudaGetSymbolAddress((void**)&whh_r, g_whh_r);
    float* hbuf;  cudaGetSymbolAddress((void**)&hbuf,  g_h);

    // Phase 0: RNA-round mma operands.
    int n4 = BATCH * SEQ * IDIM / 4;
    round_kernel<<<(n4 + 255) / 256, 256>>>((const float4*)inputs, (float4*)in_r, n4);
    n4 = G3 * IDIM / 4;
    round_kernel<<<(n4 + 255) / 256, 256>>>((const float4*)wih, (float4*)wih_r, n4);
    round_kernel<<<(n4 + 255) / 256, 256>>>((const float4*)whh, (float4*)whh_r, n4);
    n4 = BATCH * HID / 4;
    round_kernel<<<(n4 + 255) / 256, 256>>>((const float4*)h0, (float4*)hbuf, n4);

    // Phase 1: x_proj
    dim3 grid_x(G3 / 64, (BATCH * SEQ) / 128);
    xproj_tf32<<<grid_x, 256, XP_SMEM>>>(in_r, wih_r, bih);

    // Phase 2: persistent recurrence (all 512 steps in one launch)
    gru_persistent<<<NBLK, 128, GP_SMEM>>>(whh_r, bhh, h0, out);

    // Phase 3: hn
    hn_kernel<<<(BATCH * HID) / 256, 256>>>(out);
}

// round 4
// speedup vs baseline: 4.7384x; 1.0243x over previous
#include <cuda_runtime.h>
#include <math.h>
#include <stdint.h>

// GRU: inputs[64,512,1024], h0[1,64,1024], weight_ih[3072,1024], weight_hh[3072,1024],
//      bias_ih[3072], bias_hh[3072]
// out = concat(outputs[64,512,1024], hn[1,64,1024])

#define BATCH 64
#define SEQ   512
#define IDIM  1024
#define HID   1024
#define G3    3072

#define NBLK  128        // persistent blocks
#define UPB   8          // hidden units per block
#define WPAD  1028       // weight smem row stride
#define HPAD  68         // h smem row stride

// Scratch (device globals; no runtime allocation).
__device__ float g_xproj[(size_t)BATCH * SEQ * G3];   // exact fp32 x_proj
__device__ float g_in_r[(size_t)BATCH * SEQ * IDIM];  // tf32-rounded inputs
__device__ float g_wih_r[(size_t)G3 * IDIM];          // tf32-rounded W_ih
__device__ float g_whh_r[(size_t)G3 * IDIM];          // tf32-rounded W_hh
__device__ float g_h[2][(size_t)BATCH * HID];         // tf32-rounded h ping-pong
__device__ int      g_bar_count;
__device__ unsigned g_bar_gen;

// ---------------------------------------------------------------------------
// helpers
// ---------------------------------------------------------------------------
__device__ __forceinline__ float tf32r(float x) {
    uint32_t o;
    asm("cvt.rna.tf32.f32 %0, %1;" : "=r"(o) : "f"(x));
    return __uint_as_float(o);
}
__device__ __forceinline__ uint32_t smem_u32(const void* p) {
    uint32_t a;
    asm("{ .reg .u64 t; cvta.to.shared.u64 t, %1; cvt.u32.u64 %0, t; }" : "=r"(a) : "l"(p));
    return a;
}
__device__ __forceinline__ void cpa16(uint32_t dst, const void* src) {
    asm volatile("cp.async.ca.shared.global [%0], [%1], 16;" :: "r"(dst), "l"(src));
}
__device__ __forceinline__ void cpa_commit() { asm volatile("cp.async.commit_group;"); }
__device__ __forceinline__ void cpa_wait0()  { asm volatile("cp.async.wait_group 0;"); }
__device__ __forceinline__ void cpa_wait1()  { asm volatile("cp.async.wait_group 1;"); }
__device__ __forceinline__ void cpa_wait2()  { asm volatile("cp.async.wait_group 2;"); }

__device__ __forceinline__ void mma8(float* c, const uint32_t* a, uint32_t b0, uint32_t b1) {
    asm volatile(
        "mma.sync.aligned.m16n8k8.row.col.f32.tf32.tf32.f32 "
        "{%0,%1,%2,%3}, {%4,%5,%6,%7}, {%8,%9}, {%0,%1,%2,%3};"
        : "+f"(c[0]), "+f"(c[1]), "+f"(c[2]), "+f"(c[3])
        : "r"(a[0]), "r"(a[1]), "r"(a[2]), "r"(a[3]), "r"(b0), "r"(b1));
}
__device__ __forceinline__ float sigmoidf_(float x) { return 1.f / (1.f + __expf(-x)); }

__device__ __forceinline__ void grid_barrier() {
    __syncthreads();
    if (threadIdx.x == 0) {
        __threadfence();
        unsigned gen;
        asm volatile("ld.acquire.gpu.u32 %0, [%1];" : "=r"(gen) : "l"(&g_bar_gen));
        int prev = atomicAdd(&g_bar_count, 1);
        if (prev == NBLK - 1) {
            atomicExch(&g_bar_count, 0);
            asm volatile("st.release.gpu.u32 [%0], %1;" :: "l"(&g_bar_gen), "r"(gen + 1));
        } else {
            unsigned cur;
            do {
                __nanosleep(64);
                asm volatile("ld.acquire.gpu.u32 %0, [%1];" : "=r"(cur) : "l"(&g_bar_gen));
            } while (cur == gen);
        }
    }
    __syncthreads();
}

// ---------------------------------------------------------------------------
// tf32 RNA rounding pre-pass
// ---------------------------------------------------------------------------
__global__ void round_kernel(const float4* __restrict__ src, float4* __restrict__ dst, int n4)
{
    int i = blockIdx.x * 256 + threadIdx.x;
    if (i < n4) {
        float4 v = src[i];
        v.x = tf32r(v.x); v.y = tf32r(v.y); v.z = tf32r(v.z); v.w = tf32r(v.w);
        dst[i] = v;
    }
}

// ---------------------------------------------------------------------------
// x_proj GEMM v2 (tf32 mma): C[32768,3072] = A @ W^T + bias
// BM=128 BN=128 BK=16, 4-stage cp.async, 128 threads (4 warps, 2x2), 64x64 warp tile.
// ---------------------------------------------------------------------------
#define XBK   16
#define XPAD  20
#define XROWS 256    // 128 A rows + 128 B rows per stage

__global__ __launch_bounds__(128, 2)
void xproj_v2(const float* __restrict__ A,
              const float* __restrict__ W,
              const float* __restrict__ bias)
{
    extern __shared__ float sm[];            // [4][256][20]
    const uint32_t smb = smem_u32(sm);

    const int bm = blockIdx.y, bn = blockIdx.x;
    const int tid = threadIdx.x;
    const int w = tid >> 5, lane = tid & 31;
    const int g = lane >> 2, q = lane & 3;
    const int wm = (w & 1) * 64;             // warp m-origin within block
    const int wn = (w >> 1) * 64;            // warp n-origin within block

    const float* Abase = A + (size_t)bm * 128 * IDIM;
    const float* Wbase = W + (size_t)bn * 128 * IDIM;

    float acc[4][8][4];
    #pragma unroll
    for (int i = 0; i < 4; i++)
        #pragma unroll
        for (int j = 0; j < 8; j++)
            #pragma unroll
            for (int k = 0; k < 4; k++) acc[i][j][k] = 0.f;

    auto load_stage = [&](int s) {
        int buf = s & 3;
        int k0 = s * XBK;
        #pragma unroll
        for (int i = 0; i < 8; i++) {
            int idx = tid + i * 128;         // 0..1023
            int row = idx >> 2;              // 0..255
            int c   = idx & 3;               // float4 within BK
            const float* src = (row < 128)
                ? (Abase + (size_t)row * IDIM + k0 + c * 4)
                : (Wbase + (size_t)(row - 128) * IDIM + k0 + c * 4);
            cpa16(smb + (((buf * XROWS + row) * XPAD + c * 4) << 2), src);
        }
    };

    load_stage(0); cpa_commit();
    load_stage(1); cpa_commit();
    load_stage(2); cpa_commit();
    cpa_wait2();
    __syncthreads();

    for (int kc = 0; kc < 64; kc++) {
        if (kc + 3 < 64) { load_stage(kc + 3); cpa_commit(); }

        const float* S = sm + (size_t)(kc & 3) * XROWS * XPAD;
        #pragma unroll
        for (int ks = 0; ks < 2; ks++) {
            uint32_t a[4][4];
            #pragma unroll
            for (int mt = 0; mt < 4; mt++) {
                int r = wm + mt * 16;
                a[mt][0] = __float_as_uint(S[(r + g) * XPAD + ks * 8 + q]);
                a[mt][1] = __float_as_uint(S[(r + g + 8) * XPAD + ks * 8 + q]);
                a[mt][2] = __float_as_uint(S[(r + g) * XPAD + ks * 8 + q + 4]);
                a[mt][3] = __float_as_uint(S[(r + g + 8) * XPAD + ks * 8 + q + 4]);
            }
            uint32_t b0[8], b1[8];
            #pragma unroll
            for (int nt = 0; nt < 8; nt++) {
                int c = 128 + wn + nt * 8 + g;
                b0[nt] = __float_as_uint(S[c * XPAD + ks * 8 + q]);
                b1[nt] = __float_as_uint(S[c * XPAD + ks * 8 + q + 4]);
            }
            #pragma unroll
            for (int mt = 0; mt < 4; mt++)
                #pragma unroll
                for (int nt = 0; nt < 8; nt++)
                    mma8(acc[mt][nt], a[mt], b0[nt], b1[nt]);
        }

        if (kc + 1 < 64) {
            if (kc <= 60) cpa_wait2();
            else if (kc == 61) cpa_wait1();
            else cpa_wait0();
            __syncthreads();
        }
    }

    // epilogue: add bias, store
    #pragma unroll
    for (int mt = 0; mt < 4; mt++) {
        #pragma unroll
        for (int nt = 0; nt < 8; nt++) {
            int row = bm * 128 + wm + mt * 16 + g;
            int col = bn * 128 + wn + nt * 8 + 2 * q;
            float b0 = bias[col], b1 = bias[col + 1];
            *(float2*)(g_xproj + (size_t)row * G3 + col) =
                make_float2(acc[mt][nt][0] + b0, acc[mt][nt][1] + b1);
            *(float2*)(g_xproj + (size_t)(row + 8) * G3 + col) =
                make_float2(acc[mt][nt][2] + b0, acc[mt][nt][3] + b1);
        }
    }
}

// ---------------------------------------------------------------------------
// Persistent GRU recurrence (unchanged from round 3)
// ---------------------------------------------------------------------------
__global__ __launch_bounds__(128, 1)
void gru_persistent(const float* __restrict__ Whh_r,
                    const float* __restrict__ bhh,
                    const float* __restrict__ h0,
                    float* __restrict__ out)
{
    extern __shared__ float sm[];
    float* Ws = sm;                    // [24][WPAD]
    float* Hs = sm + 24 * WPAD;        // [2][64][HPAD]
    const uint32_t wsb = smem_u32(Ws);
    const uint32_t hsb = smem_u32(Hs);

    const int tid = threadIdx.x;
    const int w = tid >> 5, lane = tid & 31;
    const int g = lane >> 2, q = lane & 3;
    const int j0 = blockIdx.x * UPB;
    const int jc = j0 + 2 * q;
    const int brow[2] = { w * 16 + g, w * 16 + g + 8 };

    for (int i = tid; i < 24 * 256; i += 128) {
        int r = i >> 8, cq = i & 255;
        int gate = r >> 3, u = r & 7;
        cpa16(wsb + ((r * WPAD + cq * 4) << 2),
              Whh_r + (size_t)(gate * HID + j0 + u) * HID + cq * 4);
    }
    cpa_commit();
    cpa_wait0();
    __syncthreads();

    float2 hp2[2];
    #pragma unroll
    for (int rh = 0; rh < 2; rh++)
        hp2[rh] = *(const float2*)(h0 + (size_t)brow[rh] * HID + jc);
    float2 bh2[3];
    #pragma unroll
    for (int gate = 0; gate < 3; gate++)
        bh2[gate] = *(const float2*)(bhh + gate * HID + jc);

    float* ghb = &g_h[0][0];

    for (int t = 0; t < SEQ; t++) {
        const float* hread = ghb + (size_t)(t & 1) * BATCH * HID;
        float* hwrite      = ghb + (size_t)((t + 1) & 1) * BATCH * HID;

        float2 xg[2][3];
        #pragma unroll
        for (int rh = 0; rh < 2; rh++)
            #pragma unroll
            for (int gate = 0; gate < 3; gate++)
                xg[rh][gate] = *(const float2*)(g_xproj +
                    ((size_t)brow[rh] * SEQ + t) * G3 + gate * HID + jc);

        {
            #pragma unroll
            for (int i = 0; i < 8; i++) {
                int idx = tid + i * 128;
                int b = idx >> 4, cq = idx & 15;
                cpa16(hsb + (((0 * 64 + b) * HPAD + cq * 4) << 2),
                      hread + (size_t)b * HID + cq * 4);
            }
            cpa_commit();
        }

        float acc[3][4];
        #pragma unroll
        for (int i = 0; i < 3; i++)
            #pragma unroll
            for (int k = 0; k < 4; k++) acc[i][k] = 0.f;

        for (int kc = 0; kc < 16; kc++) {
            int cur = kc & 1;
            if (kc + 1 < 16) {
                int k0 = (kc + 1) * 64, buf = cur ^ 1;
                #pragma unroll
                for (int i = 0; i < 8; i++) {
                    int idx = tid + i * 128;
                    int b = idx >> 4, cq = idx & 15;
                    cpa16(hsb + (((buf * 64 + b) * HPAD + cq * 4) << 2),
                          hread + (size_t)b * HID + k0 + cq * 4);
                }
                cpa_commit();
                cpa_wait1();
            } else {
                cpa_wait0();
            }
            __syncthreads();

            #pragma unroll
            for (int ks = 0; ks < 8; ks++) {
                uint32_t a[4];
                int r0 = cur * 64 + w * 16;
                a[0] = __float_as_uint(Hs[(r0 + g) * HPAD + ks * 8 + q]);
                a[1] = __float_as_uint(Hs[(r0 + g + 8) * HPAD + ks * 8 + q]);
                a[2] = __float_as_uint(Hs[(r0 + g) * HPAD + ks * 8 + q + 4]);
                a[3] = __float_as_uint(Hs[(r0 + g + 8) * HPAD + ks * 8 + q + 4]);
                int koff = kc * 64 + ks * 8 + q;
                #pragma unroll
                for (int nt = 0; nt < 3; nt++) {
                    uint32_t b0 = __float_as_uint(Ws[(nt * 8 + g) * WPAD + koff]);
                    uint32_t b1 = __float_as_uint(Ws[(nt * 8 + g) * WPAD + koff + 4]);
                    mma8(acc[nt], a, b0, b1);
                }
            }
            __syncthreads();
        }

        #pragma unroll
        for (int rh = 0; rh < 2; rh++) {
            float hx[2], hr[2];
            #pragma unroll
            for (int e = 0; e < 2; e++) {
                float xr = e ? xg[rh][0].y : xg[rh][0].x;
                float xz = e ? xg[rh][1].y : xg[rh][1].x;
                float xn = e ? xg[rh][2].y : xg[rh][2].x;
                float br = e ? bh2[0].y : bh2[0].x;
                float bz = e ? bh2[1].y : bh2[1].x;
                float bn = e ? bh2[2].y : bh2[2].x;
                float hp = e ? hp2[rh].y : hp2[rh].x;
                float rr = sigmoidf_(xr + acc[0][rh * 2 + e] + br);
                float zz = sigmoidf_(xz + acc[1][rh * 2 + e] + bz);
                float nn = tanhf(xn + rr * (acc[2][rh * 2 + e] + bn));
                float hv = (1.f - zz) * nn + zz * hp;
                hx[e] = hv;
                hr[e] = tf32r(hv);
            }
            hp2[rh] = make_float2(hx[0], hx[1]);
            *(float2*)(out + ((size_t)brow[rh] * SEQ + t) * HID + jc) =
                make_float2(hx[0], hx[1]);
            *(float2*)(hwrite + (size_t)brow[rh] * HID + jc) =
                make_float2(hr[0], hr[1]);
        }

        grid_barrier();
    }
}

// Gather h_{SEQ-1} into the contiguous hn region.
__global__ void hn_kernel(float* __restrict__ out)
{
    int i = blockIdx.x * 256 + threadIdx.x;
    int b = i >> 10;
    int jj = i & 1023;
    out[(size_t)BATCH * SEQ * HID + i] =
        out[((size_t)b * SEQ + (SEQ - 1)) * HID + jj];
}

// ---------------------------------------------------------------------------
extern "C" void kernel_launch(void* const* d_in, const int* in_sizes, int n_in,
                              void* d_out, int out_size)
{
    const float* inputs = (const float*)d_in[0];
    const float* h0     = (const float*)d_in[1];
    const float* wih    = (const float*)d_in[2];
    const float* whh    = (const float*)d_in[3];
    const float* bih    = (const float*)d_in[4];
    const float* bhh    = (const float*)d_in[5];
    float* out = (float*)d_out;

    const int XP_SMEM = 4 * XROWS * XPAD * 4;                 // 81920
    const int GP_SMEM = (24 * WPAD + 2 * 64 * HPAD) * 4;      // 133504
    static bool attr_done = false;
    if (!attr_done) {
        cudaFuncSetAttribute(xproj_v2, cudaFuncAttributeMaxDynamicSharedMemorySize, XP_SMEM);
        cudaFuncSetAttribute(gru_persistent, cudaFuncAttributeMaxDynamicSharedMemorySize, GP_SMEM);
        attr_done = true;
    }

    float* in_r;  cudaGetSymbolAddress((void**)&in_r,  g_in_r);
    float* wih_r; cudaGetSymbolAddress((void**)&wih_r, g_wih_r);
    float* whh_r; cudaGetSymbolAddress((void**)&whh_r, g_whh_r);
    float* hbuf;  cudaGetSymbolAddress((void**)&hbuf,  g_h);

    // Phase 0: RNA-round mma operands.
    int n4 = BATCH * SEQ * IDIM / 4;
    round_kernel<<<(n4 + 255) / 256, 256>>>((const float4*)inputs, (float4*)in_r, n4);
    n4 = G3 * IDIM / 4;
    round_kernel<<<(n4 + 255) / 256, 256>>>((const float4*)wih, (float4*)wih_r, n4);
    round_kernel<<<(n4 + 255) / 256, 256>>>((const float4*)whh, (float4*)whh_r, n4);
    n4 = BATCH * HID / 4;
    round_kernel<<<(n4 + 255) / 256, 256>>>((const float4*)h0, (float4*)hbuf, n4);

    // Phase 1: x_proj (new 128x128x16 pipelined GEMM)
    dim3 grid_x(G3 / 128, (BATCH * SEQ) / 128);   // (24, 256)
    xproj_v2<<<grid_x, 128, XP_SMEM>>>(in_r, wih_r, bih);

    // Phase 2: persistent recurrence
    gru_persistent<<<NBLK, 128, GP_SMEM>>>(whh_r, bhh, h0, out);

    // Phase 3: hn
    hn_kernel<<<(BATCH * HID) / 256, 256>>>(out);
}